// round 16
// baseline (speedup 1.0000x reference)
#include <cuda_runtime.h>
#include <cstdint>

// Problem constants
#define BB 256
#define TT 512
#define NN 128

// ---------------- device scratch ----------------
__device__ float g_E[NN * NN];                 // exp(trans)
__device__ float g_lognorm[BB];
__device__ unsigned char g_bp[(size_t)BB * TT * NN]; // backpointers, 16.7 MB
__device__ int   g_lasttag[BB];

__device__ __forceinline__ unsigned ordf(float f) {
    unsigned u = __float_as_uint(f);
    return u ^ (((int)u >> 31) | 0x80000000u);
}

__device__ __forceinline__ void ffma2(unsigned long long& d,
                                      unsigned long long a,
                                      unsigned long long b) {
    asm("fma.rn.f32x2 %0, %1, %2, %0;" : "+l"(d) : "l"(a), "l"(b));
}

__device__ __forceinline__ unsigned long long add2(unsigned long long a,
                                                   unsigned long long b) {
    unsigned long long d;
    asm("add.rn.f32x2 %0, %1, %2;" : "=l"(d) : "l"(a), "l"(b));
    return d;
}

__device__ __forceinline__ float lo32(unsigned long long v) {
    return __uint_as_float((unsigned)v);
}
__device__ __forceinline__ float hi32(unsigned long long v) {
    return __uint_as_float((unsigned)(v >> 32));
}

// ---------------- K0: prep -----------------------------------------
__global__ void k_prep(const float* __restrict__ trans, float* __restrict__ out_trans) {
    int idx = blockIdx.x * 256 + threadIdx.x;
    if (idx < NN * NN) {
        float v = trans[idx];
        g_E[idx] = __expf(v);
        out_trans[idx] = v;
    }
}

// ---------------- K1: merged fwd + viterbi, 2 batches per block ------
// grid = 128 -> 1 block/SM. Thread j owns output state j for BOTH
// recurrences and both batches. E column in registers; trans in smem as
// packed float2 pair-rows TpS[i/2][j] = (T[2(i/2)][j], T[2(i/2)+1][j])
// -> one LDS.64 = one packed add2 operand, shared across batches.
// One __syncthreads() per time step.
__global__ __launch_bounds__(128, 1) void k_recur(const float* __restrict__ emis,
                                                  const int* __restrict__ mask,
                                                  const float* __restrict__ trans) {
    extern __shared__ unsigned long long TpS[];   // 64KB packed trans pairs

    const int p = blockIdx.x;
    const int b0 = 2 * p;
    const int b1 = b0 + 1;
    const int j = threadIdx.x;

    __shared__ __align__(16) float fbuf[2][2][NN];  // exp'd fwd alphas
    __shared__ __align__(16) float vbuf[2][2][NN];  // vit alphas
    __shared__ float csm[2][2];                     // fwd centers (alpha[0])
    __shared__ int smask[2][TT];

    const float* e0 = emis + (size_t)b0 * TT * NN;
    const float* e1 = emis + (size_t)b1 * TT * NN;

    for (int i = j; i < TT; i += NN) {
        smask[0][i] = mask[(size_t)b0 * TT + i];
        smask[1][i] = mask[(size_t)b1 * TT + i];
    }

    // build packed trans pairs in smem (coalesced LDG)
    for (int k2 = 0; k2 < 64; k2++) {
        unsigned lo = __float_as_uint(trans[(size_t)(2 * k2) * NN + j]);
        unsigned hi = __float_as_uint(trans[(size_t)(2 * k2 + 1) * NN + j]);
        TpS[k2 * NN + j] = (unsigned long long)lo | ((unsigned long long)hi << 32);
    }

    // E column in registers (coalesced LDG)
    unsigned long long E2[64];
    {
        const float* Ej = g_E + j;
        #pragma unroll
        for (int k = 0; k < 64; k++) {
            unsigned lo = __float_as_uint(Ej[(size_t)(2 * k) * NN]);
            unsigned hi = __float_as_uint(Ej[(size_t)(2 * k + 1) * NN]);
            E2[k] = (unsigned long long)lo | ((unsigned long long)hi << 32);
        }
    }

    unsigned char* bp0 = g_bp + (size_t)b0 * TT * NN;
    unsigned char* bp1 = g_bp + (size_t)b1 * TT * NN;

    // init (t = 0)
    float af0 = e0[j], af1 = e1[j];       // fwd alphas
    float av0s = af0, av1s = af1;         // vit alphas (same init)
    float cb0 = e0[0], cb1 = e1[0];       // centers of current fbuf
    fbuf[0][0][j] = __expf(af0 - cb0);
    fbuf[0][1][j] = __expf(af1 - cb1);
    vbuf[0][0][j] = av0s;
    vbuf[0][1][j] = av1s;
    if (j == 0) { csm[0][0] = af0; csm[0][1] = af1; }
    float en0 = e0[NN + j], en1 = e1[NN + j];
    int sel = 0;
    const float NEGINF = -3.402823466e38f;
    __syncthreads();

    for (int t = 1; t < TT; t++) {
        float cp0 = csm[sel][0], cp1 = csm[sel][1];   // alpha_{t-1}[0]

        // ---------- fwd dot products ----------
        unsigned long long acc0[4] = {0ull, 0ull, 0ull, 0ull};
        unsigned long long acc1[4] = {0ull, 0ull, 0ull, 0ull};
        {
            const ulonglong2* f0 = (const ulonglong2*)fbuf[sel][0];
            const ulonglong2* f1 = (const ulonglong2*)fbuf[sel][1];
            #pragma unroll
            for (int k = 0; k < 32; k++) {
                ulonglong2 v0 = f0[k];
                ulonglong2 v1 = f1[k];
                ffma2(acc0[(2 * k) & 3], v0.x, E2[2 * k]);
                ffma2(acc0[(2 * k + 1) & 3], v0.y, E2[2 * k + 1]);
                ffma2(acc1[(2 * k) & 3], v1.x, E2[2 * k]);
                ffma2(acc1[(2 * k + 1) & 3], v1.y, E2[2 * k + 1]);
            }
        }
        float s0 = 0.f, s1 = 0.f;
        #pragma unroll
        for (int q = 0; q < 4; q++) {
            s0 += lo32(acc0[q]) + hi32(acc0[q]);
            s1 += lo32(acc1[q]) + hi32(acc1[q]);
        }

        // ---------- viterbi tournament ----------
        float m0[8], m1[8];
        #pragma unroll
        for (int q = 0; q < 8; q++) { m0[q] = NEGINF; m1[q] = NEGINF; }
        {
            const ulonglong2* a0p = (const ulonglong2*)vbuf[sel][0];
            const ulonglong2* a1p = (const ulonglong2*)vbuf[sel][1];
            #pragma unroll
            for (int k = 0; k < 32; k++) {           // cands 4k..4k+3
                ulonglong2 v0 = a0p[k];
                ulonglong2 v1 = a1p[k];
                unsigned long long tp0 = TpS[(2 * k) * NN + j];
                unsigned long long tp1 = TpS[(2 * k + 1) * NN + j];
                unsigned long long w00 = add2(v0.x, tp0);
                unsigned long long w01 = add2(v0.y, tp1);
                unsigned long long w10 = add2(v1.x, tp0);
                unsigned long long w11 = add2(v1.y, tp1);
                const int q = k >> 2;
                m0[q] = fmaxf(m0[q], lo32(w00));
                m0[q] = fmaxf(m0[q], hi32(w00));
                m0[q] = fmaxf(m0[q], lo32(w01));
                m0[q] = fmaxf(m0[q], hi32(w01));
                m1[q] = fmaxf(m1[q], lo32(w10));
                m1[q] = fmaxf(m1[q], hi32(w10));
                m1[q] = fmaxf(m1[q], lo32(w11));
                m1[q] = fmaxf(m1[q], hi32(w11));
            }
        }
        float bm0 = fmaxf(fmaxf(fmaxf(m0[0], m0[1]), fmaxf(m0[2], m0[3])),
                          fmaxf(fmaxf(m0[4], m0[5]), fmaxf(m0[6], m0[7])));
        float bm1 = fmaxf(fmaxf(fmaxf(m1[0], m1[1]), fmaxf(m1[2], m1[3])),
                          fmaxf(fmaxf(m1[4], m1[5]), fmaxf(m1[6], m1[7])));

        // first group attaining the max
        int g0 = 7, g1 = 7;
        #pragma unroll
        for (int q = 6; q >= 0; q--) {
            g0 = (m0[q] == bm0) ? q : g0;
            g1 = (m1[q] == bm1) ? q : g1;
        }

        // rescan winning group (exact first index), using packed Tp
        int u0 = 15, u1 = 15;
        {
            const float* al0 = vbuf[sel][0] + 16 * g0;
            const float* al1 = vbuf[sel][1] + 16 * g1;
            float c0v[16], c1v[16];
            #pragma unroll
            for (int r = 0; r < 4; r++) {
                float4 x0 = ((const float4*)al0)[r];
                float4 x1 = ((const float4*)al1)[r];
                c0v[4 * r] = x0.x; c0v[4 * r + 1] = x0.y;
                c0v[4 * r + 2] = x0.z; c0v[4 * r + 3] = x0.w;
                c1v[4 * r] = x1.x; c1v[4 * r + 1] = x1.y;
                c1v[4 * r + 2] = x1.z; c1v[4 * r + 3] = x1.w;
            }
            const unsigned long long* tq0 = TpS + (size_t)(8 * g0) * NN + j;
            const unsigned long long* tq1 = TpS + (size_t)(8 * g1) * NN + j;
            #pragma unroll
            for (int rr = 0; rr < 8; rr++) {
                unsigned long long t0 = tq0[(size_t)rr * NN];
                unsigned long long t1 = tq1[(size_t)rr * NN];
                c0v[2 * rr]     += lo32(t0);
                c0v[2 * rr + 1] += hi32(t0);
                c1v[2 * rr]     += lo32(t1);
                c1v[2 * rr + 1] += hi32(t1);
            }
            #pragma unroll
            for (int r = 15; r >= 0; r--) {
                u0 = (c0v[r] == bm0) ? r : u0;
                u1 = (c1v[r] == bm1) ? r : u1;
            }
        }

        // ---------- shared emissions ----------
        float ec0 = en0, ec1 = en1;
        if (t + 1 < TT) {
            en0 = e0[(size_t)(t + 1) * NN + j];
            en1 = e1[(size_t)(t + 1) * NN + j];
        }
        int mk0 = smask[0][t], mk1 = smask[1][t];

        // ---------- fwd update ----------
        float nf0 = __logf(s0) + cb0 + ec0;
        float nf1 = __logf(s1) + cb1 + ec1;
        af0 = mk0 ? nf0 : af0;
        af1 = mk1 ? nf1 : af1;

        // ---------- vit update ----------
        float nv0 = bm0 + ec0;
        float nv1 = bm1 + ec1;
        av0s = mk0 ? nv0 : av0s;
        av1s = mk1 ? nv1 : av1s;
        int i0 = mk0 ? (16 * g0 + u0) : j;
        int i1 = mk1 ? (16 * g1 + u1) : j;
        bp0[(size_t)t * NN + j] = (unsigned char)i0;
        bp1[(size_t)t * NN + j] = (unsigned char)i1;

        // ---------- writes ----------
        fbuf[sel ^ 1][0][j] = __expf(af0 - cp0);
        fbuf[sel ^ 1][1][j] = __expf(af1 - cp1);
        vbuf[sel ^ 1][0][j] = av0s;
        vbuf[sel ^ 1][1][j] = av1s;
        if (j == 0) { csm[sel ^ 1][0] = af0; csm[sel ^ 1][1] = af1; }
        __syncthreads();
        cb0 = cp0; cb1 = cp1;
        sel ^= 1;
    }

    // ---------- tails: lognorm + last_tag, one warp per batch ----------
    const int wid = j >> 5;
    if (wid < 2) {
        const int l = j & 31;
        // lognorm: fbuf[sel] holds exp(a_511 - cb)
        float4 v = ((const float4*)fbuf[sel][wid])[l];
        float ts = (v.x + v.y) + (v.z + v.w);
        #pragma unroll
        for (int o = 16; o; o >>= 1) ts += __shfl_xor_sync(0xffffffffu, ts, o);
        if (l == 0) {
            float cb = wid ? cb1 : cb0;
            g_lognorm[wid ? b1 : b0] = __logf(ts) + cb;
        }
    } else {
        const int q = wid - 2;          // 0 -> b0, 1 -> b1
        const int l = j & 31;
        float4 v = ((const float4*)vbuf[sel][q])[l];
        float best = v.x; int bi = 4 * l;
        if (v.y > best) { best = v.y; bi = 4 * l + 1; }
        if (v.z > best) { best = v.z; bi = 4 * l + 2; }
        if (v.w > best) { best = v.w; bi = 4 * l + 3; }
        unsigned u = ordf(best);
        unsigned wm = __reduce_max_sync(0xffffffffu, u);
        unsigned bal = __ballot_sync(0xffffffffu, u == wm);
        int src = __ffs(bal) - 1;
        bi = __shfl_sync(0xffffffffu, bi, src);
        if (l == 0) g_lasttag[q ? b1 : b0] = bi;
    }
}

// ---------------- K2: traceback + score + ll ------------------------
// One block per batch. 128 threads: load 64KB bp slab into smem + score
// gather (overlapped). Thread 0: chase backpointers (LDS.U8 chain).
__global__ __launch_bounds__(128) void k_traceback(const float* __restrict__ emis,
                                                   const int* __restrict__ tags,
                                                   const int* __restrict__ mask,
                                                   const float* __restrict__ trans,
                                                   float* __restrict__ out_ll,
                                                   float* __restrict__ out_tags) {
    extern __shared__ unsigned char sbp[];  // 64KB
    __shared__ float sred[4];
    const int b = blockIdx.x;
    const int tid = threadIdx.x;

    const float4* src = (const float4*)(g_bp + (size_t)b * TT * NN);
    #pragma unroll
    for (int i = 0; i < 32; i++)
        ((float4*)sbp)[tid + i * 128] = src[tid + i * 128];

    // sequence score (gather + block reduce)
    {
        const float* eb = emis + (size_t)b * TT * NN;
        const int* tb = tags + (size_t)b * TT;
        const int* mb = mask + (size_t)b * TT;
        float acc = 0.f;
        for (int t = tid; t < TT; t += 128) {
            int tg = tb[t];
            float mf = (float)mb[t];
            float u = eb[(size_t)t * NN + tg] * mf;
            float bi = 0.f;
            if (t > 0) {
                int tp = tb[t - 1];
                bi = trans[tp * NN + tg] * mf;
            }
            acc += u + bi;
        }
        #pragma unroll
        for (int o = 16; o; o >>= 1) acc += __shfl_xor_sync(0xffffffffu, acc, o);
        if ((tid & 31) == 0) sred[tid >> 5] = acc;
    }
    __syncthreads();

    if (tid == 0) {
        float score = sred[0] + sred[1] + sred[2] + sred[3];
        out_ll[b] = score - g_lognorm[b];

        float* ot = out_tags + (size_t)b * TT;
        int tag = g_lasttag[b];
        ot[TT - 1] = (float)tag;
        for (int t = TT - 2; t >= 0; t--) {
            tag = sbp[(t + 1) * NN + tag];
            ot[t] = (float)tag;
        }
    }
}

// ---------------- launch ---------------------------------------------
extern "C" void kernel_launch(void* const* d_in, const int* in_sizes, int n_in,
                              void* d_out, int out_size) {
    const float* emis  = (const float*)d_in[0];
    const int*   tags  = (const int*)d_in[1];
    const int*   mask  = (const int*)d_in[2];
    const float* trans = (const float*)d_in[3];
    float* out = (float*)d_out;

    float* out_ll    = out;
    float* out_trans = out + BB;
    float* out_tags  = out + BB + NN * NN;

    const int SM64 = NN * NN * (int)sizeof(float);   // 64KB
    cudaFuncSetAttribute(k_recur, cudaFuncAttributeMaxDynamicSharedMemorySize, SM64);
    cudaFuncSetAttribute(k_traceback, cudaFuncAttributeMaxDynamicSharedMemorySize, SM64);

    k_prep<<<(NN * NN + 255) / 256, 256>>>(trans, out_trans);
    k_recur<<<BB / 2, 128, SM64>>>(emis, mask, trans);
    k_traceback<<<BB, 128, SM64>>>(emis, tags, mask, trans, out_ll, out_tags);
}